// round 5
// baseline (speedup 1.0000x reference)
#include <cuda_runtime.h>
#include <float.h>

// Problem constants (from reference)
#define NS   32
#define NH   32
#define KVH  8
#define QPK  4
#define HS   128
#define BS   16
#define MB   128
#define PART 256
#define NPARTS 8                 // MB*BS / PART = 2048/256
#define SCALE 0.08838834764831843f   // 1/sqrt(128)

#define QPAD 4
#define LPAD 8                   // logits row pad: stride 264 -> conflict-free stores

// Split-K partial scratch (4MB + 32KB)
__device__ float g_pout[(size_t)NS*KVH*QPK*NPARTS*HS];
__device__ float g_pm[NS*KVH*QPK*NPARTS];
__device__ float g_pl[NS*KVH*QPK*NPARTS];

// One CTA = (kv_head h, partition p, seq n). 256 threads.
// Phase 1: lane = 4*token + quarter. Each lane loads its 32-dim quarter of K
//          exactly once (8 LDG.128), computes 4 partial dots, combines quarters
//          with 2 shuffle stages. K traffic = minimum.
// Phase 2: lane = (s-quarter, d-row): warp V loads are fully contiguous;
//          V read exactly once; 2-stage shuffle combines the s-quarters.
__global__ __launch_bounds__(256) void attn_partial(
    const float* __restrict__ q,    const float* __restrict__ knew,
    const float* __restrict__ vnew, const float* __restrict__ kc,
    const float* __restrict__ vc,   const int*   __restrict__ bt,
    const int*   __restrict__ ctx)
{
    int h = blockIdx.x, p = blockIdx.y, n = blockIdx.z;
    int L = ctx[n];
    int start = p * PART;
    if (start >= L) return;               // uniform across CTA
    int ntok = min(PART, L - start);

    __shared__ float s_q[QPK][HS + QPAD];
    __shared__ float s_logits[QPK][PART + LPAD]; // raw logits, then exp values
    __shared__ float s_m[QPK][8];
    __shared__ float s_mf[QPK];
    __shared__ float s_lred[QPK][8];

    int tid  = threadIdx.x;
    int lane = tid & 31, w = tid >> 5;

    // Stage Q for this head-group into smem
    for (int i = tid; i < QPK * HS; i += 256) {
        int qi = i >> 7, dd = i & (HS - 1);
        s_q[qi][dd] = q[((size_t)n*NH + h*QPK + qi)*HS + dd];
    }
    __syncthreads();

    // ---- Phase 1: logits (lane = 4*token + quarter) ----
    {
        int tl  = lane >> 2;          // token within this warp's group of 8
        int qtr = lane & 3;           // 32-dim quarter owned by this lane

#pragma unroll
        for (int pass = 0; pass < 4; pass++) {
            int t  = start + pass*64 + w*8 + tl;
            int tc = min(t, L - 1);   // clamp: invalid lanes re-read a cached token
            int blk = bt[n*MB + (tc >> 4)];
            const float* base = kc + ((size_t)blk*KVH + h)*(HS*BS) + (tc & 15)*8;

            float dot[QPK] = {0.f, 0.f, 0.f, 0.f};
#pragma unroll
            for (int cc = 0; cc < 8; cc++) {
                int c = qtr*8 + cc;   // float4 chunk of head-dim (qtr constant/lane)
                float4 kv = *(const float4*)(base + (c >> 1)*128 + (c & 1)*4);
#pragma unroll
                for (int k2 = 0; k2 < QPK; k2++) {
                    float4 qv = *(const float4*)&s_q[k2][qtr*32 + cc*4];
                    dot[k2] += kv.x*qv.x + kv.y*qv.y + kv.z*qv.z + kv.w*qv.w;
                }
            }
            // combine the 4 quarters (lane bits 0..1); convergent (no divergence)
#pragma unroll
            for (int k2 = 0; k2 < QPK; k2++) {
                dot[k2] += __shfl_xor_sync(0xffffffffu, dot[k2], 1);
                dot[k2] += __shfl_xor_sync(0xffffffffu, dot[k2], 2);
            }
            if (t < L) s_logits[qtr][t - start] = dot[qtr] * SCALE;
        }
    }
    __syncthreads();

    // Override the new token's logit: its K comes from `knew`, not the cache.
    {
        int tn = L - 1;
        if (tn >= start && tn < start + PART) {   // uniform across CTA
            if (w < QPK) {                        // warp w handles head w
                const float4* kp = (const float4*)(knew + ((size_t)n*KVH + h)*HS);
                float4 kv = kp[lane];
                float4 qv = *(const float4*)&s_q[w][lane*4];
                float dot = kv.x*qv.x + kv.y*qv.y + kv.z*qv.z + kv.w*qv.w;
#pragma unroll
                for (int off = 16; off; off >>= 1)
                    dot += __shfl_xor_sync(0xffffffffu, dot, off);
                if (lane == 0) s_logits[w][tn - start] = dot * SCALE;
            }
            __syncthreads();
        }
    }

    // ---- max + exp + sum over the partition (token = tid) ----
    float lg[QPK], mloc[QPK];
#pragma unroll
    for (int k = 0; k < QPK; k++) {
        lg[k]   = (tid < ntok) ? s_logits[k][tid] : -FLT_MAX;
        mloc[k] = lg[k];
    }
#pragma unroll
    for (int off = 16; off; off >>= 1)
#pragma unroll
        for (int k = 0; k < QPK; k++)
            mloc[k] = fmaxf(mloc[k], __shfl_xor_sync(0xffffffffu, mloc[k], off));
    if (lane == 0)
#pragma unroll
        for (int k = 0; k < QPK; k++) s_m[k][w] = mloc[k];
    __syncthreads();
    if (tid < QPK) {
        float m = s_m[tid][0];
#pragma unroll
        for (int i = 1; i < 8; i++) m = fmaxf(m, s_m[tid][i]);
        s_mf[tid] = m;
    }
    __syncthreads();

    float lsum[QPK];
#pragma unroll
    for (int k = 0; k < QPK; k++) {
        float e = (tid < ntok) ? __expf(lg[k] - s_mf[k]) : 0.f;
        s_logits[k][tid] = e;
        lsum[k] = e;
    }
#pragma unroll
    for (int off = 16; off; off >>= 1)
#pragma unroll
        for (int k = 0; k < QPK; k++)
            lsum[k] += __shfl_xor_sync(0xffffffffu, lsum[k], off);
    if (lane == 0)
#pragma unroll
        for (int k = 0; k < QPK; k++) s_lred[k][w] = lsum[k];
    __syncthreads();

    if (tid < QPK) {
        float l = 0.f;
#pragma unroll
        for (int i = 0; i < 8; i++) l += s_lred[tid][i];
        int pid = ((n*KVH + h)*QPK + tid)*NPARTS + p;
        g_pm[pid] = s_mf[tid];
        g_pl[pid] = l;
    }

    // ---- Phase 2: V accumulation, fully coalesced ----
    // Thread handles d0 = tid>>2 and d1 = d0+64 at s positions s4*4..s4*4+3.
    int s4 = tid & 3;
    int db = tid >> 2;                  // 0..63
    float acc[QPK][2];
#pragma unroll
    for (int k = 0; k < QPK; k++) acc[k][0] = acc[k][1] = 0.f;

    int nblk = (ntok + 15) >> 4;
    for (int b = 0; b < nblk; b++) {
        int blk = bt[n*MB + (start >> 4) + b];
        const float* vbase = vc + ((size_t)blk*KVH + h)*(HS*BS);
        float4 w4[QPK];
#pragma unroll
        for (int k = 0; k < QPK; k++)
            w4[k] = *(const float4*)&s_logits[k][b*16 + s4*4];
        float4 v0 = *(const float4*)(vbase + db*BS + s4*4);
        float4 v1 = *(const float4*)(vbase + (db + 64)*BS + s4*4);
#pragma unroll
        for (int k = 0; k < QPK; k++) {
            acc[k][0] += w4[k].x*v0.x + w4[k].y*v0.y + w4[k].z*v0.z + w4[k].w*v0.w;
            acc[k][1] += w4[k].x*v1.x + w4[k].y*v1.y + w4[k].z*v1.z + w4[k].w*v1.w;
        }
    }

    // Correct the new token: replace stale cached V with v_new contribution.
    int tl = L - 1;
    if (tl >= start && tl < start + ntok && ((tl & 15) >> 2) == s4) {
        int blk = bt[n*MB + (tl >> 4)];
        int s   = tl & 15;
        const float* vbase = vc + ((size_t)blk*KVH + h)*(HS*BS);
        float vst0 = vbase[db*BS + s];
        float vst1 = vbase[(db + 64)*BS + s];
        float vn0  = vnew[((size_t)n*KVH + h)*HS + db];
        float vn1  = vnew[((size_t)n*KVH + h)*HS + db + 64];
        float d0 = vn0 - vst0, d1 = vn1 - vst1;
#pragma unroll
        for (int k = 0; k < QPK; k++) {
            float wv = s_logits[k][tl - start];
            acc[k][0] += wv * d0;
            acc[k][1] += wv * d1;
        }
    }

    // Combine the 4 s-quarters (lane bits 0..1)
#pragma unroll
    for (int k = 0; k < QPK; k++) {
#pragma unroll
        for (int j = 0; j < 2; j++) {
            acc[k][j] += __shfl_xor_sync(0xffffffffu, acc[k][j], 1);
            acc[k][j] += __shfl_xor_sync(0xffffffffu, acc[k][j], 2);
        }
    }
    if (s4 == 0) {
#pragma unroll
        for (int k = 0; k < QPK; k++) {
            size_t pid = (size_t)((n*KVH + h)*QPK + k)*NPARTS + p;
            g_pout[pid*HS + db]      = acc[k][0];
            g_pout[pid*HS + db + 64] = acc[k][1];
        }
    }
}

// One CTA per (n, h, qi): combine up to NPARTS partials, normalize, write out.
__global__ __launch_bounds__(128) void attn_reduce(
    const int* __restrict__ ctx, float* __restrict__ out)
{
    int g = blockIdx.x;                 // (n*KVH + h)*QPK + qi
    int n = g / (KVH*QPK);
    int head = g % (KVH*QPK);
    int L = ctx[n];
    int np = (L + PART - 1) / PART;
    int d = threadIdx.x;

    float pm[NPARTS], pl[NPARTS], ov[NPARTS];
#pragma unroll
    for (int p = 0; p < NPARTS; p++) {
        bool ok = p < np;
        pm[p] = ok ? g_pm[g*NPARTS + p] : -FLT_MAX;
        pl[p] = ok ? g_pl[g*NPARTS + p] : 0.f;
        ov[p] = ok ? g_pout[((size_t)g*NPARTS + p)*HS + d] : 0.f;
    }
    float m = pm[0];
#pragma unroll
    for (int p = 1; p < NPARTS; p++) m = fmaxf(m, pm[p]);
    float l = 0.f, o = 0.f;
#pragma unroll
    for (int p = 0; p < NPARTS; p++) {
        float a = __expf(pm[p] - m);
        l += a * pl[p];
        o += a * ov[p];
    }
    out[((size_t)n*NH + head)*HS + d] = o / l;
}

extern "C" void kernel_launch(void* const* d_in, const int* in_sizes, int n_in,
                              void* d_out, int out_size)
{
    const float* q   = (const float*)d_in[0];
    const float* k   = (const float*)d_in[1];
    const float* v   = (const float*)d_in[2];
    const float* kc  = (const float*)d_in[3];
    const float* vc  = (const float*)d_in[4];
    const int*   bt  = (const int*)d_in[5];
    const int*   ctx = (const int*)d_in[6];

    dim3 g1(KVH, NPARTS, NS);
    attn_partial<<<g1, 256>>>(q, k, v, kc, vc, bt, ctx);
    attn_reduce<<<NS*KVH*QPK, 128>>>(ctx, (float*)d_out);
}

// round 6
// speedup vs baseline: 1.4506x; 1.4506x over previous
#include <cuda_runtime.h>
#include <float.h>

// Problem constants (from reference)
#define NS   32
#define NH   32
#define KVH  8
#define QPK  4
#define HS   128
#define BS   16
#define MB   128
#define PART 256
#define NPARTS 8                 // MB*BS / PART = 2048/256
#define SCALE 0.08838834764831843f   // 1/sqrt(128)

#define QPAD 4

// Split-K partial scratch (4MB + 32KB)
__device__ float g_pout[(size_t)NS*KVH*QPK*NPARTS*HS];
__device__ float g_pm[NS*KVH*QPK*NPARTS];
__device__ float g_pl[NS*KVH*QPK*NPARTS];

// One CTA = (kv_head h, partition p, seq n). 256 threads.
// Phase 1 (R2): lane = 4*token + qhead; each lane computes a full 128-dim dot
//          (no shuffles). K loads dedup 4-ways across q-head lanes.
// Phase 2 (R4): lane = (s-quarter, d-row): warp V loads fully contiguous;
//          V read exactly once; 2-stage shuffle combines the s-quarters.
__global__ __launch_bounds__(256) void attn_partial(
    const float* __restrict__ q,    const float* __restrict__ knew,
    const float* __restrict__ vnew, const float* __restrict__ kc,
    const float* __restrict__ vc,   const int*   __restrict__ bt,
    const int*   __restrict__ ctx)
{
    int h = blockIdx.x, p = blockIdx.y, n = blockIdx.z;
    int L = ctx[n];
    int start = p * PART;
    if (start >= L) return;               // uniform across CTA
    int ntok = min(PART, L - start);

    __shared__ float s_q[QPK][HS + QPAD];
    __shared__ float s_logits[QPK][PART]; // raw logits, then exp values
    __shared__ float s_m[QPK][8];
    __shared__ float s_mf[QPK];
    __shared__ float s_lred[QPK][8];

    int tid  = threadIdx.x;
    int lane = tid & 31, w = tid >> 5;

    // Stage Q for this head-group into smem (padded rows)
    for (int i = tid; i < QPK * HS; i += 256) {
        int qi = i >> 7, dd = i & (HS - 1);
        s_q[qi][dd] = q[((size_t)n*NH + h*QPK + qi)*HS + dd];
    }
    __syncthreads();

    // ---- Phase 1: logits, shuffle-free (exact R2 scheme) ----
    int tl_ = lane >> 2;          // token within this warp's group of 8
    int qi  = lane & 3;           // query head within group
    const float4* q4 = (const float4*)s_q[qi];

    for (int pass = 0; pass < PART / 64; pass++) {
        int t = start + pass*64 + w*8 + tl_;
        if (t < L && t - start < PART) {
            float dot = 0.f;
            if (t == L - 1) {
                // new token's K comes from the `key` input (cache not written)
                const float4* kp = (const float4*)(knew + ((size_t)n*KVH + h)*HS);
#pragma unroll 8
                for (int c = 0; c < 32; c++) {
                    float4 kv = kp[c];
                    float4 qv = q4[c];
                    dot += kv.x*qv.x + kv.y*qv.y + kv.z*qv.z + kv.w*qv.w;
                }
            } else {
                int blk = bt[n*MB + (t >> 4)];
                int s   = t & 15;
                // key_cache[b,h,d,s,x]: chunk c -> head dims 4c..4c+3
                const float* base = kc + ((size_t)blk*KVH + h)*(HS*BS) + s*8;
#pragma unroll 8
                for (int c = 0; c < 32; c++) {
                    float4 kv = *(const float4*)(base + (c >> 1)*128 + (c & 1)*4);
                    float4 qv = q4[c];
                    dot += kv.x*qv.x + kv.y*qv.y + kv.z*qv.z + kv.w*qv.w;
                }
            }
            s_logits[qi][t - start] = dot * SCALE;
        }
    }
    __syncthreads();

    // ---- max + exp + sum over the partition (token = tid) ----
    float lg[QPK], mloc[QPK];
#pragma unroll
    for (int k = 0; k < QPK; k++) {
        lg[k]   = (tid < ntok) ? s_logits[k][tid] : -FLT_MAX;
        mloc[k] = lg[k];
    }
#pragma unroll
    for (int off = 16; off; off >>= 1)
#pragma unroll
        for (int k = 0; k < QPK; k++)
            mloc[k] = fmaxf(mloc[k], __shfl_xor_sync(0xffffffffu, mloc[k], off));
    if (lane == 0)
#pragma unroll
        for (int k = 0; k < QPK; k++) s_m[k][w] = mloc[k];
    __syncthreads();
    if (tid < QPK) {
        float m = s_m[tid][0];
#pragma unroll
        for (int i = 1; i < 8; i++) m = fmaxf(m, s_m[tid][i]);
        s_mf[tid] = m;
    }
    __syncthreads();

    float lsum[QPK];
#pragma unroll
    for (int k = 0; k < QPK; k++) {
        float e = (tid < ntok) ? __expf(lg[k] - s_mf[k]) : 0.f;
        s_logits[k][tid] = e;
        lsum[k] = e;
    }
#pragma unroll
    for (int off = 16; off; off >>= 1)
#pragma unroll
        for (int k = 0; k < QPK; k++)
            lsum[k] += __shfl_xor_sync(0xffffffffu, lsum[k], off);
    if (lane == 0)
#pragma unroll
        for (int k = 0; k < QPK; k++) s_lred[k][w] = lsum[k];
    __syncthreads();

    if (tid < QPK) {
        float l = 0.f;
#pragma unroll
        for (int i = 0; i < 8; i++) l += s_lred[tid][i];
        int pid = ((n*KVH + h)*QPK + tid)*NPARTS + p;
        g_pm[pid] = s_mf[tid];
        g_pl[pid] = l;
    }

    // ---- Phase 2: V accumulation, fully coalesced (R4 scheme) ----
    // Thread handles d0 = tid>>2 and d1 = d0+64 at s positions s4*4..s4*4+3.
    int s4 = tid & 3;
    int db = tid >> 2;                  // 0..63
    float acc[QPK][2];
#pragma unroll
    for (int k = 0; k < QPK; k++) acc[k][0] = acc[k][1] = 0.f;

    int nblk = (ntok + 15) >> 4;
    for (int b = 0; b < nblk; b++) {
        int blk = bt[n*MB + (start >> 4) + b];
        const float* vbase = vc + ((size_t)blk*KVH + h)*(HS*BS);
        float4 w4[QPK];
#pragma unroll
        for (int k = 0; k < QPK; k++)
            w4[k] = *(const float4*)&s_logits[k][b*16 + s4*4];
        float4 v0 = *(const float4*)(vbase + db*BS + s4*4);
        float4 v1 = *(const float4*)(vbase + (db + 64)*BS + s4*4);
#pragma unroll
        for (int k = 0; k < QPK; k++) {
            acc[k][0] += w4[k].x*v0.x + w4[k].y*v0.y + w4[k].z*v0.z + w4[k].w*v0.w;
            acc[k][1] += w4[k].x*v1.x + w4[k].y*v1.y + w4[k].z*v1.z + w4[k].w*v1.w;
        }
    }

    // Correct the new token: replace stale cached V with v_new contribution.
    int tl = L - 1;
    if (tl >= start && tl < start + ntok && ((tl & 15) >> 2) == s4) {
        int blk = bt[n*MB + (tl >> 4)];
        int s   = tl & 15;
        const float* vbase = vc + ((size_t)blk*KVH + h)*(HS*BS);
        float vst0 = vbase[db*BS + s];
        float vst1 = vbase[(db + 64)*BS + s];
        float vn0  = vnew[((size_t)n*KVH + h)*HS + db];
        float vn1  = vnew[((size_t)n*KVH + h)*HS + db + 64];
        float d0 = vn0 - vst0, d1 = vn1 - vst1;
#pragma unroll
        for (int k = 0; k < QPK; k++) {
            float wv = s_logits[k][tl - start];
            acc[k][0] += wv * d0;
            acc[k][1] += wv * d1;
        }
    }

    // Combine the 4 s-quarters (lane bits 0..1)
#pragma unroll
    for (int k = 0; k < QPK; k++) {
#pragma unroll
        for (int j = 0; j < 2; j++) {
            acc[k][j] += __shfl_xor_sync(0xffffffffu, acc[k][j], 1);
            acc[k][j] += __shfl_xor_sync(0xffffffffu, acc[k][j], 2);
        }
    }
    if (s4 == 0) {
#pragma unroll
        for (int k = 0; k < QPK; k++) {
            size_t pid = (size_t)((n*KVH + h)*QPK + k)*NPARTS + p;
            g_pout[pid*HS + db]      = acc[k][0];
            g_pout[pid*HS + db + 64] = acc[k][1];
        }
    }
}

// One CTA per (n, h, qi): combine up to NPARTS partials, normalize, write out.
__global__ __launch_bounds__(128) void attn_reduce(
    const int* __restrict__ ctx, float* __restrict__ out)
{
    int g = blockIdx.x;                 // (n*KVH + h)*QPK + qi
    int n = g / (KVH*QPK);
    int head = g % (KVH*QPK);
    int L = ctx[n];
    int np = (L + PART - 1) / PART;
    int d = threadIdx.x;

    float pm[NPARTS], pl[NPARTS], ov[NPARTS];
#pragma unroll
    for (int p = 0; p < NPARTS; p++) {
        bool ok = p < np;
        pm[p] = ok ? g_pm[g*NPARTS + p] : -FLT_MAX;
        pl[p] = ok ? g_pl[g*NPARTS + p] : 0.f;
        ov[p] = ok ? g_pout[((size_t)g*NPARTS + p)*HS + d] : 0.f;
    }
    float m = pm[0];
#pragma unroll
    for (int p = 1; p < NPARTS; p++) m = fmaxf(m, pm[p]);
    float l = 0.f, o = 0.f;
#pragma unroll
    for (int p = 0; p < NPARTS; p++) {
        float a = __expf(pm[p] - m);
        l += a * pl[p];
        o += a * ov[p];
    }
    out[((size_t)n*NH + head)*HS + d] = o / l;
}

extern "C" void kernel_launch(void* const* d_in, const int* in_sizes, int n_in,
                              void* d_out, int out_size)
{
    const float* q   = (const float*)d_in[0];
    const float* k   = (const float*)d_in[1];
    const float* v   = (const float*)d_in[2];
    const float* kc  = (const float*)d_in[3];
    const float* vc  = (const float*)d_in[4];
    const int*   bt  = (const int*)d_in[5];
    const int*   ctx = (const int*)d_in[6];

    dim3 g1(KVH, NPARTS, NS);
    attn_partial<<<g1, 256>>>(q, k, v, kc, vc, bt, ctx);
    attn_reduce<<<NS*KVH*QPK, 128>>>(ctx, (float*)d_out);
}